// round 1
// baseline (speedup 1.0000x reference)
#include <cuda_runtime.h>
#include <cuda_bf16.h>

// Problem: loss = sum_{pos} softplus(-p)/n_pos + sum_{neg} softplus(p)/n_neg
// over 8192x8192 = 64Mi elements. Pure streaming reduction, HBM-bound.

#define NBLOCKS  1184        // 148 SMs * 8 CTAs
#define NTHREADS 256
#define N_TOTAL  67108864    // 8192*8192
#define N_VEC4   16777216    // N_TOTAL / 4

// Scratch for per-block partials (no device mallocs allowed).
__device__ float g_pos[NBLOCKS];
__device__ float g_neg[NBLOCKS];
__device__ int   g_cnt[NBLOCKS];

// softplus split: softplus(x)  = log1p(e^{-|x|}) + max(x, 0)
//                 softplus(-x) = log1p(e^{-|x|}) + max(-x, 0)
// Shared log-term -> one EX2 + one LG2 per element regardless of label.
__device__ __forceinline__ void lane_accum(float x, int y,
                                           float& pos, float& neg, int& cnt) {
    float ax     = fabsf(x);
    float common = __logf(1.0f + __expf(-ax));   // log1p(e^{-|x|}) in [0, ln2]
    bool  ispos  = (y != 0);
    // relu part of the softplus for the side this element belongs to
    float relu   = fmaxf(ispos ? -x : x, 0.0f);
    float v      = common + relu;
    pos += ispos ? v : 0.0f;
    neg += ispos ? 0.0f : v;
    cnt += ispos ? 1 : 0;
}

__global__ __launch_bounds__(NTHREADS)
void reduce_stage1(const float4* __restrict__ pred,
                   const int4*  __restrict__ ty) {
    float pos = 0.0f, neg = 0.0f;
    int   cnt = 0;

    const int stride = gridDim.x * blockDim.x;
    for (int i = blockIdx.x * blockDim.x + threadIdx.x; i < N_VEC4; i += stride) {
        float4 p = __ldcs(pred + i);   // streaming: evict-first, data is touched once
        int4   y = __ldcs(ty + i);
        lane_accum(p.x, y.x, pos, neg, cnt);
        lane_accum(p.y, y.y, pos, neg, cnt);
        lane_accum(p.z, y.z, pos, neg, cnt);
        lane_accum(p.w, y.w, pos, neg, cnt);
    }

    // warp reduction (fixed tree -> deterministic)
    #pragma unroll
    for (int o = 16; o > 0; o >>= 1) {
        pos += __shfl_down_sync(0xFFFFFFFFu, pos, o);
        neg += __shfl_down_sync(0xFFFFFFFFu, neg, o);
        cnt += __shfl_down_sync(0xFFFFFFFFu, cnt, o);
    }

    __shared__ float sp[NTHREADS / 32];
    __shared__ float sn[NTHREADS / 32];
    __shared__ int   sc[NTHREADS / 32];
    int wid = threadIdx.x >> 5;
    int lid = threadIdx.x & 31;
    if (lid == 0) { sp[wid] = pos; sn[wid] = neg; sc[wid] = cnt; }
    __syncthreads();

    if (wid == 0) {
        constexpr int NW = NTHREADS / 32;
        float bp = (lid < NW) ? sp[lid] : 0.0f;
        float bn = (lid < NW) ? sn[lid] : 0.0f;
        int   bc = (lid < NW) ? sc[lid] : 0;
        #pragma unroll
        for (int o = NW / 2; o > 0; o >>= 1) {
            bp += __shfl_down_sync(0xFFFFFFFFu, bp, o);
            bn += __shfl_down_sync(0xFFFFFFFFu, bn, o);
            bc += __shfl_down_sync(0xFFFFFFFFu, bc, o);
        }
        if (lid == 0) {
            g_pos[blockIdx.x] = bp;
            g_neg[blockIdx.x] = bn;
            g_cnt[blockIdx.x] = bc;
        }
    }
}

__global__ __launch_bounds__(1024)
void reduce_stage2(float* __restrict__ out) {
    float pos = 0.0f, neg = 0.0f;
    int   cnt = 0;
    for (int i = threadIdx.x; i < NBLOCKS; i += blockDim.x) {
        pos += g_pos[i];
        neg += g_neg[i];
        cnt += g_cnt[i];
    }
    #pragma unroll
    for (int o = 16; o > 0; o >>= 1) {
        pos += __shfl_down_sync(0xFFFFFFFFu, pos, o);
        neg += __shfl_down_sync(0xFFFFFFFFu, neg, o);
        cnt += __shfl_down_sync(0xFFFFFFFFu, cnt, o);
    }
    __shared__ float sp[32];
    __shared__ float sn[32];
    __shared__ int   sc[32];
    int wid = threadIdx.x >> 5;
    int lid = threadIdx.x & 31;
    if (lid == 0) { sp[wid] = pos; sn[wid] = neg; sc[wid] = cnt; }
    __syncthreads();
    if (wid == 0) {
        float bp = (lid < 32) ? sp[lid] : 0.0f;
        float bn = (lid < 32) ? sn[lid] : 0.0f;
        int   bc = (lid < 32) ? sc[lid] : 0;
        #pragma unroll
        for (int o = 16; o > 0; o >>= 1) {
            bp += __shfl_down_sync(0xFFFFFFFFu, bp, o);
            bn += __shfl_down_sync(0xFFFFFFFFu, bn, o);
            bc += __shfl_down_sync(0xFFFFFFFFu, bc, o);
        }
        if (lid == 0) {
            float n_pos = (float)bc;
            float n_neg = (float)(N_TOTAL - bc);
            out[0] = bp / n_pos + bn / n_neg;
        }
    }
}

extern "C" void kernel_launch(void* const* d_in, const int* in_sizes, int n_in,
                              void* d_out, int out_size) {
    const float4* pred = (const float4*)d_in[0];  // pred_y: float32 [8192,8192]
    const int4*   ty   = (const int4*)  d_in[1];  // true_y: int32   [8192,8192]
    float*        out  = (float*)d_out;

    reduce_stage1<<<NBLOCKS, NTHREADS>>>(pred, ty);
    reduce_stage2<<<1, 1024>>>(out);
}